// round 9
// baseline (speedup 1.0000x reference)
#include <cuda_runtime.h>
#include <cuda_fp16.h>

#define NN 100000
#define EE 1600000
#define EPSF 1e-12f
#define CAP 64   // slots per dst node; in-degree is Poisson(16), P(>=64) ~ 1e-21

// ---------------- bit-cast helpers ------------------------------------------
__device__ __forceinline__ unsigned int h2_to_u32(__half2 v) {
    return *reinterpret_cast<unsigned int*>(&v);
}

// ---------------- scratch (static device globals) ---------------------------
__device__ __align__(128) float g_outdeg[3][NN];
__device__ __align__(128) float g_indeg[3][NN];
__device__ __align__(128) int   g_cnt[3][NN];
__device__ __align__(128) long long g_slot[3][(size_t)NN * CAP]; // packed (nw<<32 | src)
__device__ __align__(128) __half g_hh[NN * 64];  // transformed features (fp16)
__device__ __align__(128) float  g_y[NN * 64];   // per-layer outputs t = agg/deg + b (fp32)

// ---------------- zero: counters + degree arrays (tiny) ----------------------
__global__ void zero_kernel() {
    int i = blockIdx.x * blockDim.x + threadIdx.x;
    if (i >= NN) return;
#pragma unroll
    for (int l = 0; l < 3; l++) {
        g_outdeg[l][i] = 0.f;
        g_indeg[l][i] = 0.f;
        g_cnt[l][i] = 0;
    }
}

// ---------------- weighted-degree sums: one layer ----------------------------
__global__ void edge_deg1_kernel(const int* __restrict__ src, const int* __restrict__ dst,
                                 const float* __restrict__ w, int layer) {
    int e = blockIdx.x * blockDim.x + threadIdx.x;
    if (e >= EE) return;
    float wv = w[e];
    atomicAdd(&g_outdeg[layer][src[e]], wv);
    atomicAdd(&g_indeg[layer][dst[e]], wv);
}

// ---------------- weighted-degree sums: layers 2 & 3 -------------------------
__global__ void edge_deg23_kernel(const int* __restrict__ s2, const int* __restrict__ d2, const float* __restrict__ w2,
                                  const int* __restrict__ s3, const int* __restrict__ d3, const float* __restrict__ w3) {
    int idx = blockIdx.x * blockDim.x + threadIdx.x;
    if (idx >= 2 * EE) return;
    int layer = 1 + (idx >= EE);
    int e = (idx >= EE) ? idx - EE : idx;
    const int* src = (layer == 1) ? s2 : s3;
    const int* dst = (layer == 1) ? d2 : d3;
    const float* w = (layer == 1) ? w2 : w3;
    float wv = w[e];
    atomicAdd(&g_outdeg[layer][src[e]], wv);
    atomicAdd(&g_indeg[layer][dst[e]], wv);
}

// ---------------- slotted CSR build: norm + slot grab + packed store ---------
__global__ void build_kernel(const int* __restrict__ src, const int* __restrict__ dst,
                             const float* __restrict__ w, int layer) {
    int e = blockIdx.x * blockDim.x + threadIdx.x;
    if (e >= EE) return;
    int s = src[e], d = dst[e];
    float nw = w[e] * rsqrtf(fmaxf(g_outdeg[layer][s] * g_indeg[layer][d], EPSF));
    int p = atomicAdd(&g_cnt[layer][d], 1);
    long long pk = ((long long)(unsigned)__float_as_uint(nw) << 32) | (unsigned)s;
    g_slot[layer][(size_t)d * CAP + p] = pk;
}

// ---------------- dense GEMM: g_hh = in @ W (fp32 in, fp16 out) -------------
template <int DIN, int DOUT>
__global__ void gemm_kernel(const float* __restrict__ x, const float* __restrict__ W) {
    __shared__ float sW[DIN * DOUT];
    for (int i = threadIdx.x; i < DIN * DOUT; i += blockDim.x) sW[i] = W[i];
    __syncthreads();

    constexpr int TPR = DOUT / 4;
    const int rowsPerBlock = blockDim.x / TPR;
    int row = blockIdx.x * rowsPerBlock + threadIdx.x / TPR;
    int cg = (threadIdx.x % TPR) * 4;
    if (row >= NN) return;

    float a0 = 0.f, a1 = 0.f, a2 = 0.f, a3 = 0.f;
    const float4* x4 = reinterpret_cast<const float4*>(x + (size_t)row * DIN);
#pragma unroll
    for (int k4 = 0; k4 < DIN / 4; k4++) {
        float4 xv = __ldg(&x4[k4]);
#pragma unroll
        for (int j = 0; j < 4; j++) {
            float xs = (j == 0) ? xv.x : (j == 1) ? xv.y : (j == 2) ? xv.z : xv.w;
            const float4 wv = *reinterpret_cast<const float4*>(&sW[(k4 * 4 + j) * DOUT + cg]);
            a0 += xs * wv.x; a1 += xs * wv.y; a2 += xs * wv.z; a3 += xs * wv.w;
        }
    }
    uint2 pk;
    pk.x = h2_to_u32(__floats2half2_rn(a0, a1));
    pk.y = h2_to_u32(__floats2half2_rn(a2, a3));
    *reinterpret_cast<uint2*>(g_hh + (size_t)row * DOUT + cg) = pk;
}

// ---------------- gather aggregate (DOUT=64): warp per node ------------------
// One edge per iteration, 32 lanes x half2 = 128B row gather, register acc.
// Writes y = acc/deg + bias (fp32).
__global__ void gather64_kernel(const float* __restrict__ bias, float* __restrict__ outp, int layer) {
    int node = (blockIdx.x * blockDim.x + threadIdx.x) >> 5;
    if (node >= NN) return;
    int lane = threadIdx.x & 31;

    int cnt = g_cnt[layer][node];
    const long long* slots = g_slot[layer] + (size_t)node * CAP;

    float accx = 0.f, accy = 0.f, degsum = 0.f;
    for (int base = 0; base < cnt; base += 32) {
        int n = min(32, cnt - base);
        long long pk = 0;
        if (lane < n) pk = slots[base + lane];
        int s = (int)(unsigned)(pk & 0xffffffffLL);
        float nw = __uint_as_float((unsigned)((unsigned long long)pk >> 32));
        degsum += nw;  // nw==0 for lane>=n
#pragma unroll 4
        for (int i = 0; i < n; i++) {
            int ss = __shfl_sync(0xffffffffu, s, i);
            float nn = __shfl_sync(0xffffffffu, nw, i);
            __half2 hv = *reinterpret_cast<const __half2*>(g_hh + (size_t)ss * 64 + lane * 2);
            float2 f = __half22float2(hv);
            accx += nn * f.x;
            accy += nn * f.y;
        }
    }
#pragma unroll
    for (int o = 16; o; o >>= 1) degsum += __shfl_xor_sync(0xffffffffu, degsum, o);
    float inv = 1.f / fmaxf(degsum, EPSF);

    float2 r;
    r.x = accx * inv + __ldg(&bias[lane * 2]);
    r.y = accy * inv + __ldg(&bias[lane * 2 + 1]);
    *reinterpret_cast<float2*>(outp + (size_t)node * 64 + lane * 2) = r;
}

// ---------------- gather aggregate (DOUT=32): warp per node ------------------
// Two edges per iteration: 16 lanes x half2 per edge (64B row), cross-half
// combine at the end via shfl_xor(16).
__global__ void gather32_kernel(const float* __restrict__ bias, float* __restrict__ outp, int layer) {
    int node = (blockIdx.x * blockDim.x + threadIdx.x) >> 5;
    if (node >= NN) return;
    int lane = threadIdx.x & 31;
    int sub = lane >> 4;     // which of the 2 edges this half-warp covers
    int l = lane & 15;       // feature-pair index

    int cnt = g_cnt[layer][node];
    const long long* slots = g_slot[layer] + (size_t)node * CAP;

    float accx = 0.f, accy = 0.f, degsum = 0.f;
    for (int base = 0; base < cnt; base += 32) {
        int n = min(32, cnt - base);
        long long pk = 0;
        if (lane < n) pk = slots[base + lane];
        int s = (int)(unsigned)(pk & 0xffffffffLL);
        float nw = __uint_as_float((unsigned)((unsigned long long)pk >> 32));
        degsum += nw;  // nw==0 for lane>=n
#pragma unroll 4
        for (int i = 0; i < n; i += 2) {
            int idx = i + sub;  // may be ==n on odd tail: nw there is 0, contributes 0
            int ss = __shfl_sync(0xffffffffu, s, idx & 31);
            float nn = __shfl_sync(0xffffffffu, nw, idx & 31);
            __half2 hv = *reinterpret_cast<const __half2*>(g_hh + (size_t)ss * 32 + l * 2);
            float2 f = __half22float2(hv);
            accx += nn * f.x;
            accy += nn * f.y;
        }
    }
    // combine the two half-warp partial sums (same features, different edges)
    accx += __shfl_xor_sync(0xffffffffu, accx, 16);
    accy += __shfl_xor_sync(0xffffffffu, accy, 16);
#pragma unroll
    for (int o = 16; o; o >>= 1) degsum += __shfl_xor_sync(0xffffffffu, degsum, o);
    float inv = 1.f / fmaxf(degsum, EPSF);

    if (lane < 16) {
        float2 r;
        r.x = accx * inv + __ldg(&bias[l * 2]);
        r.y = accy * inv + __ldg(&bias[l * 2 + 1]);
        *reinterpret_cast<float2*>(outp + (size_t)node * 32 + l * 2) = r;
    }
}

// ---------------- launch ------------------------------------------------------
extern "C" void kernel_launch(void* const* d_in, const int* in_sizes, int n_in,
                              void* d_out, int out_size) {
    const float* x    = (const float*)d_in[0];
    const int*   src1 = (const int*)d_in[1];
    const int*   dst1 = (const int*)d_in[2];
    const float* w1   = (const float*)d_in[3];
    const int*   src2 = (const int*)d_in[4];
    const int*   dst2 = (const int*)d_in[5];
    const float* w2   = (const float*)d_in[6];
    const int*   src3 = (const int*)d_in[7];
    const int*   dst3 = (const int*)d_in[8];
    const float* w3   = (const float*)d_in[9];
    const float* W1   = (const float*)d_in[10];
    const float* b1   = (const float*)d_in[11];
    const float* W2   = (const float*)d_in[12];
    const float* b2   = (const float*)d_in[13];
    const float* W3   = (const float*)d_in[14];
    const float* b3   = (const float*)d_in[15];
    float* out = (float*)d_out;

    // One-time host-side setup (first call = correctness run, outside capture).
    static float* p_y = nullptr;
    static cudaStream_t s2 = nullptr;
    static cudaEvent_t evZero = nullptr, evB2 = nullptr, evB3 = nullptr;
    if (!p_y) {
        cudaGetSymbolAddress((void**)&p_y, g_y);
        cudaStreamCreateWithFlags(&s2, cudaStreamNonBlocking);
        cudaEventCreateWithFlags(&evZero, cudaEventDisableTiming);
        cudaEventCreateWithFlags(&evB2, cudaEventDisableTiming);
        cudaEventCreateWithFlags(&evB3, cudaEventDisableTiming);
    }

    const int B = 256;
    const int gridN  = (NN + B - 1) / B;
    const int gridE  = (EE + B - 1) / B;
    const int gridE2 = (2 * EE + B - 1) / B;
    const int gridGather = (NN * 32 + B - 1) / B;  // 1 warp per node

    // ---- main: zero first ----
    zero_kernel<<<gridN, B>>>();
    cudaEventRecord(evZero, 0);

    // ---- s2: degrees + builds for layers 2 & 3 (feature-independent) ----
    cudaStreamWaitEvent(s2, evZero, 0);
    edge_deg23_kernel<<<gridE2, B, 0, s2>>>(src2, dst2, w2, src3, dst3, w3);
    build_kernel<<<gridE, B, 0, s2>>>(src2, dst2, w2, 1);
    cudaEventRecord(evB2, s2);
    build_kernel<<<gridE, B, 0, s2>>>(src3, dst3, w3, 2);
    cudaEventRecord(evB3, s2);

    // ---- main: layer-1 chain ----
    gemm_kernel<128, 64><<<NN / 16, B>>>(x, W1);          // h1 = x @ W1 (fp16)
    edge_deg1_kernel<<<gridE, B>>>(src1, dst1, w1, 0);
    build_kernel<<<gridE, B>>>(src1, dst1, w1, 0);
    gather64_kernel<<<gridGather, B>>>(b1, p_y, 0);       // y1 = agg1/deg1 + b1

    // ---- layer 2 ----
    gemm_kernel<64, 32><<<NN / 32, B>>>(p_y, W2);         // h2 = y1 @ W2 (fp16)
    cudaStreamWaitEvent(0, evB2, 0);
    gather32_kernel<<<gridGather, B>>>(b2, p_y, 1);       // y2 = agg2/deg2 + b2

    // ---- layer 3 ----
    gemm_kernel<32, 32><<<NN / 32, B>>>(p_y, W3);         // h3 = y2 @ W3 (fp16)
    cudaStreamWaitEvent(0, evB3, 0);
    gather32_kernel<<<gridGather, B>>>(b3, out, 2);       // out = agg3/deg3 + b3

    (void)in_sizes; (void)n_in; (void)out_size;
}